// round 15
// baseline (speedup 1.0000x reference)
#include <cuda_runtime.h>
#include <cuda_fp16.h>
#include <math.h>

constexpr int NA = 50000;
constexpr int NT = 25000;
constexpr int DIN = 32;
constexpr int H = 64;
constexpr int E_AA = 800000;
constexpr int E_AT = 400000;
constexpr int E_TA = 400000;

constexpr int OFF_AA   = 0;
constexpr int OFF_AT_S = NA;
constexpr int OFF_TA_D = 2 * NA;
constexpr int OFF_AT_D = 3 * NA;
constexpr int OFF_TA_S = 3 * NA + NT;
constexpr int NTOT = 3 * NA + 2 * NT;

constexpr int NBLK_A = (NA + 1023) / 1024;
constexpr int NBLK_T = (NT + 1023) / 1024;
constexpr int NBLK   = NBLK_A + NBLK_T;

// scratch
__device__ int    g_cnt[NTOT];          // zero-init at load; re-zeroed at tail of each launch
__device__ float  g_dda[NA];            // 1/(deg_aa+1), computed in scan_local
__device__ __half g_h16_A[(size_t)(NA + NT) * H];   // unified: [0,NA)=h_aa, [NA,..)=h_ta
__device__ __half g_h16_at[(size_t)NA * H];         // agent->target features
__device__ float4 g_acc_a[(size_t)NA * H / 4];
__device__ float4 g_acc_t[(size_t)NT * H / 4];
// CSR (built once per launch)
__device__ int  g_rs_a[NA + 1];
__device__ int  g_rs_t[NT + 1];
__device__ int  g_cur_a[NA];
__device__ int  g_cur_t[NT];
__device__ int2 g_ent_a[E_AA + E_TA];
__device__ int2 g_ent_t[E_AT];
__device__ int  g_part[NBLK];
__device__ int  g_partscan[NBLK];

// ---------------------------------------------------------------------------
__global__ void zero_cnt_kernel() {
    int i = blockIdx.x * blockDim.x + threadIdx.x;
    if (i < NTOT) g_cnt[i] = 0;
}

// dst histograms (needed by scan): dst_aa, dst_at, dst_ta. 4 edges/thread.
__global__ void count_dst_kernel(const int* __restrict__ dst_aa,
                                 const int* __restrict__ dst_at,
                                 const int* __restrict__ dst_ta) {
    constexpr int G_AA = E_AA / 4, G_AT = E_AT / 4, G_TA = E_TA / 4;
    int i = blockIdx.x * blockDim.x + threadIdx.x;
    const int* p; int off, j;
    if (i < G_AA)                   { p = dst_aa; off = OFF_AA;   j = i; }
    else if (i < G_AA + G_AT)       { p = dst_at; off = OFF_AT_D; j = i - G_AA; }
    else if (i < G_AA + G_AT + G_TA){ p = dst_ta; off = OFF_TA_D; j = i - G_AA - G_AT; }
    else return;
    int4 v = *(const int4*)(p + j * 4);
    atomicAdd(&g_cnt[off + v.x], 1);
    atomicAdd(&g_cnt[off + v.y], 1);
    atomicAdd(&g_cnt[off + v.z], 1);
    atomicAdd(&g_cnt[off + v.w], 1);
}

// src histograms (needed only by fill): src_at, src_ta. Runs on side stream.
__global__ void count_src_kernel(const int* __restrict__ src_at,
                                 const int* __restrict__ src_ta) {
    constexpr int G_AT = E_AT / 4, G_TA = E_TA / 4;
    int i = blockIdx.x * blockDim.x + threadIdx.x;
    const int* p; int off, j;
    if (i < G_AT)             { p = src_at; off = OFF_AT_S; j = i; }
    else if (i < G_AT + G_TA) { p = src_ta; off = OFF_TA_S; j = i - G_AT; }
    else return;
    int4 v = *(const int4*)(p + j * 4);
    atomicAdd(&g_cnt[off + v.x], 1);
    atomicAdd(&g_cnt[off + v.y], 1);
    atomicAdd(&g_cnt[off + v.z], 1);
    atomicAdd(&g_cnt[off + v.w], 1);
}

__global__ __launch_bounds__(1024) void scan_local_kernel() {
    __shared__ int sm[1024];
    int b = blockIdx.x;
    bool isA = (b < NBLK_A);
    int base = isA ? b * 1024 : (b - NBLK_A) * 1024;
    int n = isA ? NA : NT;
    int tid = threadIdx.x;
    int i = base + tid;
    int v = 0;
    if (i < n) {
        if (isA) {
            int caa = g_cnt[OFF_AA + i];
            v = caa + g_cnt[OFF_TA_D + i];
            g_cur_a[i] = 0;
            g_dda[i] = 1.0f / ((float)caa + 1.0f);   // dis_aa^2 for agg epilogues
        } else {
            v = g_cnt[OFF_AT_D + i];
            g_cur_t[i] = 0;
        }
    }
    sm[tid] = v;
    __syncthreads();
#pragma unroll
    for (int off = 1; off < 1024; off <<= 1) {
        int u = (tid >= off) ? sm[tid - off] : 0;
        __syncthreads();
        sm[tid] += u;
        __syncthreads();
    }
    if (i < n) {
        int excl = sm[tid] - v;
        if (isA) g_rs_a[i] = excl; else g_rs_t[i] = excl;
    }
    if (tid == 1023) g_part[b] = sm[1023];
}

__global__ void scan_mid_kernel() {
    __shared__ int sp[NBLK];
    __shared__ int so[NBLK + 2];
    int tid = threadIdx.x;
    if (tid < NBLK) sp[tid] = g_part[tid];
    __syncthreads();
    if (tid == 0) {
        int s = 0;
        for (int b = 0; b < NBLK_A; b++) { so[b] = s; s += sp[b]; }
        so[NBLK] = s;
        s = 0;
        for (int b = NBLK_A; b < NBLK; b++) { so[b] = s; s += sp[b]; }
        so[NBLK + 1] = s;
    }
    __syncthreads();
    if (tid < NBLK) g_partscan[tid] = so[tid];
    if (tid == 0) { g_rs_a[NA] = so[NBLK]; g_rs_t[NT] = so[NBLK + 1]; }
}

__global__ __launch_bounds__(1024) void scan_add_kernel() {
    int b = blockIdx.x;
    if (b == 0) return;
    bool isA = (b < NBLK_A);
    if (!isA && b == NBLK_A) return;
    int base = isA ? b * 1024 : (b - NBLK_A) * 1024;
    int n = isA ? NA : NT;
    int i = base + threadIdx.x;
    int off = g_partscan[b];
    if (i < n) { if (isA) g_rs_a[i] += off; else g_rs_t[i] += off; }
}

// Vectorized fill: 4 edges/thread via int4 loads of src/dst.
__global__ void fill_kernel(const int* __restrict__ src_aa, const int* __restrict__ dst_aa,
                            const int* __restrict__ src_ta, const int* __restrict__ dst_ta,
                            const int* __restrict__ src_at, const int* __restrict__ dst_at) {
    constexpr int G_AA = E_AA / 4, G_TA = E_TA / 4, G_AT = E_AT / 4;
    int i = blockIdx.x * blockDim.x + threadIdx.x;
    if (i < G_AA) {
        int4 s4 = *(const int4*)(src_aa + i * 4);
        int4 d4 = *(const int4*)(dst_aa + i * 4);
        int ss[4] = {s4.x, s4.y, s4.z, s4.w};
        int dd[4] = {d4.x, d4.y, d4.z, d4.w};
#pragma unroll
        for (int e = 0; e < 4; e++) {
            float w = rsqrtf((float)g_cnt[OFF_AA + ss[e]] + 1.0f)
                    * rsqrtf((float)g_cnt[OFF_AA + dd[e]] + 1.0f);
            int pos = g_rs_a[dd[e]] + atomicAdd(&g_cur_a[dd[e]], 1);
            g_ent_a[pos] = make_int2(ss[e], __float_as_int(w));
        }
    } else if (i < G_AA + G_TA) {
        int j = i - G_AA;
        int4 s4 = *(const int4*)(src_ta + j * 4);
        int4 d4 = *(const int4*)(dst_ta + j * 4);
        int ss[4] = {s4.x, s4.y, s4.z, s4.w};
        int dd[4] = {d4.x, d4.y, d4.z, d4.w};
#pragma unroll
        for (int e = 0; e < 4; e++) {
            float w = rsqrtf((float)g_cnt[OFF_TA_S + ss[e]])
                    * rsqrtf((float)g_cnt[OFF_TA_D + dd[e]]);
            int pos = g_rs_a[dd[e]] + atomicAdd(&g_cur_a[dd[e]], 1);
            g_ent_a[pos] = make_int2(NA + ss[e], __float_as_int(w));
        }
    } else if (i < G_AA + G_TA + G_AT) {
        int j = i - G_AA - G_TA;
        int4 s4 = *(const int4*)(src_at + j * 4);
        int4 d4 = *(const int4*)(dst_at + j * 4);
        int ss[4] = {s4.x, s4.y, s4.z, s4.w};
        int dd[4] = {d4.x, d4.y, d4.z, d4.w};
#pragma unroll
        for (int e = 0; e < 4; e++) {
            float w = rsqrtf((float)g_cnt[OFF_AT_S + ss[e]])
                    * rsqrtf((float)g_cnt[OFF_AT_D + dd[e]]);
            int pos = g_rs_t[dd[e]] + atomicAdd(&g_cur_t[dd[e]], 1);
            g_ent_t[pos] = make_int2(ss[e], __float_as_int(w));
        }
    }
}

// Agent transform: writes ONLY fp16 feature buffers. 512 threads, BM=64, 128 cols.
template <int K, bool RELU>
__global__ __launch_bounds__(512, 3) void transform_agent_kernel(
        const float4* __restrict__ x,
        const float* __restrict__ Wa, const float* __restrict__ Wb) {
    __shared__ float xs[64][K];
    __shared__ float Ws[K][128];
    int tid = threadIdx.x;
    int row0 = blockIdx.x * 64;
    for (int i = tid; i < K * 64; i += 512) {
        int k = i >> 6, c = i & 63;
        Ws[k][c]      = Wa[i];
        Ws[k][c + 64] = Wb[i];
    }
    constexpr int KV = K / 4;
    for (int i = tid; i < 64 * KV; i += 512) {
        int r = i / KV, kv = i - r * KV;
        int row = row0 + r;
        float4 v = (row < NA) ? x[(size_t)row * KV + kv] : make_float4(0.f, 0.f, 0.f, 0.f);
        if (RELU) { v.x = fmaxf(v.x, 0.f); v.y = fmaxf(v.y, 0.f);
                    v.z = fmaxf(v.z, 0.f); v.w = fmaxf(v.w, 0.f); }
        *(float4*)&xs[r][kv * 4] = v;
    }
    __syncthreads();
    int ty = tid >> 5, tx = tid & 31;
    int r0 = ty * 4, c0 = tx * 4;
    float acc[4][4];
#pragma unroll
    for (int i = 0; i < 4; i++)
#pragma unroll
        for (int j = 0; j < 4; j++) acc[i][j] = 0.f;
#pragma unroll 4
    for (int k = 0; k < K; k++) {
        float w[4];
        *(float4*)&w[0] = *(float4*)&Ws[k][c0];
#pragma unroll
        for (int i = 0; i < 4; i++) {
            float xv = xs[r0 + i][k];
#pragma unroll
            for (int j = 0; j < 4; j++) acc[i][j] = fmaf(xv, w[j], acc[i][j]);
        }
    }
    bool is_a = (c0 < 64);
    int cc = is_a ? c0 : (c0 - 64);
#pragma unroll
    for (int i = 0; i < 4; i++) {
        int row = row0 + r0 + i;
        if (row >= NA) continue;
        __half2 h0 = __floats2half2_rn(acc[i][0], acc[i][1]);
        __half2 h1 = __floats2half2_rn(acc[i][2], acc[i][3]);
        uint2 hpk; hpk.x = *(unsigned*)&h0; hpk.y = *(unsigned*)&h1;
        if (is_a) *(uint2*)(g_h16_A  + (size_t)row * H + cc) = hpk;
        else      *(uint2*)(g_h16_at + (size_t)row * H + cc) = hpk;
    }
}

// Target transform -> g_h16_A rows [NA, NA+NT). 256 threads.
template <int K, bool RELU>
__global__ __launch_bounds__(256, 4) void transform_target_kernel(
        const float4* __restrict__ x, const float* __restrict__ W) {
    __shared__ float xs[64][K];
    __shared__ float Ws[K][64];
    int tid = threadIdx.x;
    int row0 = blockIdx.x * 64;
    for (int i = tid; i < K * 64; i += 256) {
        int k = i >> 6, c = i & 63;
        Ws[k][c] = W[i];
    }
    constexpr int KV = K / 4;
    for (int i = tid; i < 64 * KV; i += 256) {
        int r = i / KV, kv = i - r * KV;
        int row = row0 + r;
        float4 v = (row < NT) ? x[(size_t)row * KV + kv] : make_float4(0.f, 0.f, 0.f, 0.f);
        if (RELU) { v.x = fmaxf(v.x, 0.f); v.y = fmaxf(v.y, 0.f);
                    v.z = fmaxf(v.z, 0.f); v.w = fmaxf(v.w, 0.f); }
        *(float4*)&xs[r][kv * 4] = v;
    }
    __syncthreads();
    int ty = tid >> 4, tx = tid & 15;
    int r0 = ty * 4, c0 = tx * 4;
    float acc[4][4];
#pragma unroll
    for (int i = 0; i < 4; i++)
#pragma unroll
        for (int j = 0; j < 4; j++) acc[i][j] = 0.f;
#pragma unroll 4
    for (int k = 0; k < K; k++) {
        float w[4];
        *(float4*)&w[0] = *(float4*)&Ws[k][c0];
#pragma unroll
        for (int i = 0; i < 4; i++) {
            float xv = xs[r0 + i][k];
#pragma unroll
            for (int j = 0; j < 4; j++) acc[i][j] = fmaf(xv, w[j], acc[i][j]);
        }
    }
#pragma unroll
    for (int i = 0; i < 4; i++) {
        int row = row0 + r0 + i;
        if (row >= NT) continue;
        __half2 h0 = __floats2half2_rn(acc[i][0], acc[i][1]);
        __half2 h1 = __floats2half2_rn(acc[i][2], acc[i][3]);
        uint2 u; u.x = *(unsigned*)&h0; u.y = *(unsigned*)&h1;
        *(uint2*)(g_h16_A + (size_t)(NA + row) * H + c0) = u;
    }
}

// Shared gather body: warp accumulates weighted fp16 rows from feat via CSR entries.
__device__ __forceinline__ void gather_seg(const int2* __restrict__ ent,
                                           const __half* __restrict__ feat,
                                           int beg, int end, int grp, int sub,
                                           float* a) {
    for (int p = beg + grp; p < end; p += 8) {
        int p2 = p + 4;
        int2 e1 = __ldg(&ent[p]);
        int2 e2 = (p2 < end) ? __ldg(&ent[p2]) : make_int2(0, 0);
        float w1 = __int_as_float(e1.y);
        float w2 = __int_as_float(e2.y);
        uint4 r1 = *(const uint4*)(feat + (size_t)e1.x * H + sub * 8);
        uint4 r2 = *(const uint4*)(feat + (size_t)e2.x * H + sub * 8);
        float2 f;
        f = __half22float2(*(__half2*)&r1.x); a[0] = fmaf(f.x, w1, a[0]); a[1] = fmaf(f.y, w1, a[1]);
        f = __half22float2(*(__half2*)&r1.y); a[2] = fmaf(f.x, w1, a[2]); a[3] = fmaf(f.y, w1, a[3]);
        f = __half22float2(*(__half2*)&r1.z); a[4] = fmaf(f.x, w1, a[4]); a[5] = fmaf(f.y, w1, a[5]);
        f = __half22float2(*(__half2*)&r1.w); a[6] = fmaf(f.x, w1, a[6]); a[7] = fmaf(f.y, w1, a[7]);
        f = __half22float2(*(__half2*)&r2.x); a[0] = fmaf(f.x, w2, a[0]); a[1] = fmaf(f.y, w2, a[1]);
        f = __half22float2(*(__half2*)&r2.y); a[2] = fmaf(f.x, w2, a[2]); a[3] = fmaf(f.y, w2, a[3]);
        f = __half22float2(*(__half2*)&r2.z); a[4] = fmaf(f.x, w2, a[4]); a[5] = fmaf(f.y, w2, a[5]);
        f = __half22float2(*(__half2*)&r2.w); a[6] = fmaf(f.x, w2, a[6]); a[7] = fmaf(f.y, w2, a[7]);
    }
#pragma unroll
    for (int j = 0; j < 8; j++) {
        a[j] += __shfl_down_sync(0xFFFFFFFFu, a[j], 16);
        a[j] += __shfl_down_sync(0xFFFFFFFFu, a[j], 8);
    }
}

// Layer-1 aggregation: writes acc_a / acc_t in fp32 (combined, one launch).
__global__ __launch_bounds__(256) void agg1_kernel(const float* __restrict__ b_aa,
                                                   const float* __restrict__ b_ta,
                                                   const float* __restrict__ b_at) {
    int gw = (blockIdx.x * 256 + threadIdx.x) >> 5;
    int lane = threadIdx.x & 31;
    int grp = lane >> 3, sub = lane & 7;
    float a[8];
#pragma unroll
    for (int j = 0; j < 8; j++) a[j] = 0.f;
    if (gw < NA) {
        gather_seg(g_ent_a, g_h16_A, g_rs_a[gw], g_rs_a[gw + 1], grp, sub, a);
        if (grp == 0) {
            float dd = g_dda[gw];
            uint4 rs = *(const uint4*)(g_h16_A + (size_t)gw * H + sub * 8);
            float2 s0 = __half22float2(*(__half2*)&rs.x);
            float2 s1 = __half22float2(*(__half2*)&rs.y);
            float2 s2 = __half22float2(*(__half2*)&rs.z);
            float2 s3 = __half22float2(*(__half2*)&rs.w);
            int c = sub * 8;
            float4 b0, b1;
            b0.x = a[0] + dd * s0.x + b_aa[c + 0] + b_ta[c + 0];
            b0.y = a[1] + dd * s0.y + b_aa[c + 1] + b_ta[c + 1];
            b0.z = a[2] + dd * s1.x + b_aa[c + 2] + b_ta[c + 2];
            b0.w = a[3] + dd * s1.y + b_aa[c + 3] + b_ta[c + 3];
            b1.x = a[4] + dd * s2.x + b_aa[c + 4] + b_ta[c + 4];
            b1.y = a[5] + dd * s2.y + b_aa[c + 5] + b_ta[c + 5];
            b1.z = a[6] + dd * s3.x + b_aa[c + 6] + b_ta[c + 6];
            b1.w = a[7] + dd * s3.y + b_aa[c + 7] + b_ta[c + 7];
            size_t base = (size_t)gw * (H / 4) + sub * 2;
            g_acc_a[base] = b0; g_acc_a[base + 1] = b1;
        }
    } else if (gw < NA + NT) {
        int node = gw - NA;
        gather_seg(g_ent_t, g_h16_at, g_rs_t[node], g_rs_t[node + 1], grp, sub, a);
        if (grp == 0) {
            int c = sub * 8;
            float4 b0 = make_float4(a[0] + b_at[c],     a[1] + b_at[c + 1],
                                    a[2] + b_at[c + 2], a[3] + b_at[c + 3]);
            float4 b1 = make_float4(a[4] + b_at[c + 4], a[5] + b_at[c + 5],
                                    a[6] + b_at[c + 6], a[7] + b_at[c + 7]);
            size_t base = (size_t)node * (H / 4) + sub * 2;
            g_acc_t[base] = b0; g_acc_t[base + 1] = b1;
        }
    }
}

// Layer-2 aggregation with fused projection (combined, one launch) -> out.
__global__ __launch_bounds__(256) void agg2_kernel(
        const float* __restrict__ b2_aa, const float* __restrict__ b2_ta,
        const float* __restrict__ b2_at,
        const float* __restrict__ Wp_a, const float* __restrict__ bp_a,
        const float* __restrict__ Wp_t, const float* __restrict__ bp_t,
        float* __restrict__ out) {
    int gw = (blockIdx.x * 256 + threadIdx.x) >> 5;
    int lane = threadIdx.x & 31;
    int grp = lane >> 3, sub = lane & 7;
    float a[8];
#pragma unroll
    for (int j = 0; j < 8; j++) a[j] = 0.f;
    float p0 = 0.f, p1 = 0.f;
    float bias0, bias1;
    if (gw < NA) {
        gather_seg(g_ent_a, g_h16_A, g_rs_a[gw], g_rs_a[gw + 1], grp, sub, a);
        if (grp == 0) {
            float dd = g_dda[gw];
            uint4 rs = *(const uint4*)(g_h16_A + (size_t)gw * H + sub * 8);
            float2 s0 = __half22float2(*(__half2*)&rs.x);
            float2 s1 = __half22float2(*(__half2*)&rs.y);
            float2 s2 = __half22float2(*(__half2*)&rs.z);
            float2 s3 = __half22float2(*(__half2*)&rs.w);
            float sv[8] = {s0.x, s0.y, s1.x, s1.y, s2.x, s2.y, s3.x, s3.y};
            int c = sub * 8;
#pragma unroll
            for (int j = 0; j < 8; j++) {
                float v = a[j] + dd * sv[j] + b2_aa[c + j] + b2_ta[c + j];
                p0 = fmaf(v, Wp_a[(c + j) * 2 + 0], p0);
                p1 = fmaf(v, Wp_a[(c + j) * 2 + 1], p1);
            }
        }
        bias0 = bp_a[0]; bias1 = bp_a[1];
    } else if (gw < NA + NT) {
        int node = gw - NA;
        gather_seg(g_ent_t, g_h16_at, g_rs_t[node], g_rs_t[node + 1], grp, sub, a);
        if (grp == 0) {
            int c = sub * 8;
#pragma unroll
            for (int j = 0; j < 8; j++) {
                float v = a[j] + b2_at[c + j];
                p0 = fmaf(v, Wp_t[(c + j) * 2 + 0], p0);
                p1 = fmaf(v, Wp_t[(c + j) * 2 + 1], p1);
            }
        }
        bias0 = bp_t[0]; bias1 = bp_t[1];
    } else return;
#pragma unroll
    for (int off = 4; off; off >>= 1) {
        p0 += __shfl_down_sync(0xFFFFFFFFu, p0, off);
        p1 += __shfl_down_sync(0xFFFFFFFFu, p1, off);
    }
    if (lane == 0)
        *(float2*)(out + (size_t)gw * 2) = make_float2(p0 + bias0, p1 + bias1);
}

// ---------------------------------------------------------------------------
static inline int cdiv(long long a, int b) { return (int)((a + b - 1) / b); }

extern "C" void kernel_launch(void* const* d_in, const int* in_sizes, int n_in,
                              void* d_out, int out_size) {
    const float* x_agent  = (const float*)d_in[1];
    const float* x_target = (const float*)d_in[2];
    const int* src_aa = (const int*)d_in[3];
    const int* dst_aa = (const int*)d_in[4];
    const int* src_at = (const int*)d_in[5];
    const int* dst_at = (const int*)d_in[6];
    const int* src_ta = (const int*)d_in[7];
    const int* dst_ta = (const int*)d_in[8];
    const float* W1_aa = (const float*)d_in[9];
    const float* b1_aa = (const float*)d_in[10];
    const float* W1_at = (const float*)d_in[11];
    const float* b1_at = (const float*)d_in[12];
    const float* W1_ta = (const float*)d_in[13];
    const float* b1_ta = (const float*)d_in[14];
    const float* W2_aa = (const float*)d_in[15];
    const float* b2_aa = (const float*)d_in[16];
    const float* W2_at = (const float*)d_in[17];
    const float* b2_at = (const float*)d_in[18];
    const float* W2_ta = (const float*)d_in[19];
    const float* b2_ta = (const float*)d_in[20];
    const float* Wp_agent  = (const float*)d_in[21];
    const float* bp_agent  = (const float*)d_in[22];
    const float* Wp_target = (const float*)d_in[23];
    const float* bp_target = (const float*)d_in[24];
    float* out = (float*)d_out;

    void *p_acca, *p_acct;
    cudaGetSymbolAddress(&p_acca, g_acc_a);
    cudaGetSymbolAddress(&p_acct, g_acc_t);
    float* acc_a = (float*)p_acca;
    float* acc_t = (float*)p_acct;

    static cudaStream_t s2 = nullptr;
    static cudaEvent_t evFork = nullptr, evSrc = nullptr, evL1 = nullptr,
                       evFill = nullptr, evZ = nullptr, evFork2 = nullptr, evTT = nullptr;
    if (s2 == nullptr) {
        cudaStreamCreateWithFlags(&s2, cudaStreamNonBlocking);
        cudaEventCreateWithFlags(&evFork,  cudaEventDisableTiming);
        cudaEventCreateWithFlags(&evSrc,   cudaEventDisableTiming);
        cudaEventCreateWithFlags(&evL1,    cudaEventDisableTiming);
        cudaEventCreateWithFlags(&evFill,  cudaEventDisableTiming);
        cudaEventCreateWithFlags(&evZ,     cudaEventDisableTiming);
        cudaEventCreateWithFlags(&evFork2, cudaEventDisableTiming);
        cudaEventCreateWithFlags(&evTT,    cudaEventDisableTiming);
    }

    // g_cnt is zeroed (module-load on first call; tail zero on every call).

    // ---- fork: s2 runs src-degree counts then layer-1 transforms ----
    cudaEventRecord(evFork, 0);
    cudaStreamWaitEvent(s2, evFork, 0);
    constexpr long long SRC_G = (E_AT + (long long)E_TA) / 4;
    count_src_kernel<<<cdiv(SRC_G, 256), 256, 0, s2>>>(src_at, src_ta);
    cudaEventRecord(evSrc, s2);
    transform_agent_kernel<DIN, false><<<cdiv(NA, 64), 512, 0, s2>>>(
        (const float4*)x_agent, W1_aa, W1_at);
    transform_target_kernel<DIN, false><<<cdiv(NT, 64), 256, 0, s2>>>(
        (const float4*)x_target, W1_ta);
    cudaEventRecord(evL1, s2);

    // ---- main: dst counts -> scan (computes g_dda) -> fill ----
    constexpr long long DST_G = ((long long)E_AA + E_AT + E_TA) / 4;
    count_dst_kernel<<<cdiv(DST_G, 256), 256>>>(dst_aa, dst_at, dst_ta);
    scan_local_kernel<<<NBLK, 1024>>>();
    scan_mid_kernel<<<1, 128>>>();
    scan_add_kernel<<<NBLK, 1024>>>();
    cudaStreamWaitEvent(0, evSrc, 0);
    constexpr long long E_G = ((long long)E_AA + E_TA + E_AT) / 4;
    fill_kernel<<<cdiv(E_G, 256), 256>>>(src_aa, dst_aa, src_ta, dst_ta, src_at, dst_at);
    cudaEventRecord(evFill, 0);

    // ---- s2 tail: re-zero counts for the next call (overlaps agg1) ----
    cudaStreamWaitEvent(s2, evFill, 0);
    zero_cnt_kernel<<<cdiv(NTOT, 256), 256, 0, s2>>>();
    cudaEventRecord(evZ, s2);

    // ---- join L1, layer-1 aggregate ----
    cudaStreamWaitEvent(0, evL1, 0);
    constexpr long long AGG_THREADS = (long long)(NA + NT) * 32;
    agg1_kernel<<<cdiv(AGG_THREADS, 256), 256>>>(b1_aa, b1_ta, b1_at);

    // ---- fork 2: layer-2 transforms (agent on main, target on s2) ----
    cudaEventRecord(evFork2, 0);
    cudaStreamWaitEvent(s2, evFork2, 0);
    transform_target_kernel<H, true><<<cdiv(NT, 64), 256, 0, s2>>>(
        (const float4*)acc_t, W2_ta);
    cudaEventRecord(evTT, s2);
    transform_agent_kernel<H, true><<<cdiv(NA, 64), 512>>>(
        (const float4*)acc_a, W2_aa, W2_at);
    cudaStreamWaitEvent(0, evTT, 0);

    // ---- layer-2 aggregate with fused projection ----
    agg2_kernel<<<cdiv(AGG_THREADS, 256), 256>>>(
        b2_aa, b2_ta, b2_at, Wp_agent, bp_agent, Wp_target, bp_target, out);
    cudaStreamWaitEvent(0, evZ, 0);   // rejoin s2 tail so capture is well-formed
}

// round 16
// speedup vs baseline: 1.1708x; 1.1708x over previous
#include <cuda_runtime.h>
#include <cuda_fp16.h>
#include <math.h>

constexpr int NA = 50000;
constexpr int NT = 25000;
constexpr int DIN = 32;
constexpr int H = 64;
constexpr int E_AA = 800000;
constexpr int E_AT = 400000;
constexpr int E_TA = 400000;

constexpr int OFF_AA   = 0;
constexpr int OFF_AT_S = NA;
constexpr int OFF_TA_D = 2 * NA;
constexpr int OFF_AT_D = 3 * NA;
constexpr int OFF_TA_S = 3 * NA + NT;
constexpr int NTOT = 3 * NA + 2 * NT;

constexpr int NBLK_A = (NA + 1023) / 1024;
constexpr int NBLK_T = (NT + 1023) / 1024;
constexpr int NBLK   = NBLK_A + NBLK_T;

// scratch
__device__ int    g_cnt[NTOT];
__device__ __half g_h16_A[(size_t)(NA + NT) * H];   // layer1 feats: [0,NA)=x@W1_aa, [NA,..)=x_t@W1_ta
__device__ __half g_h16_at[(size_t)NA * H];         // x@W1_at (agent->target)
__device__ __half g_frelu[(size_t)(NA + NT) * H];   // relu(layer1 acc), unified rows
// composite projection matrices and bias constants
__device__ float g_Va[H * 2];    // W2_aa @ Wp_agent
__device__ float g_Vt[H * 2];    // W2_ta @ Wp_agent
__device__ float g_Vat[H * 2];   // W2_at @ Wp_target
__device__ float g_cb[4];        // {agent bias0, agent bias1, target bias0, target bias1}
// CSR (built once per launch)
__device__ int  g_rs_a[NA + 1];
__device__ int  g_rs_t[NT + 1];
__device__ int  g_cur_a[NA];
__device__ int  g_cur_t[NT];
__device__ int2 g_ent_a[E_AA + E_TA];
__device__ int2 g_ent_t[E_AT];
__device__ int  g_part[NBLK];
__device__ int  g_partscan[NBLK];

// ---------------------------------------------------------------------------
__global__ void zero_cnt_kernel() {
    int i = blockIdx.x * blockDim.x + threadIdx.x;
    if (i < NTOT) g_cnt[i] = 0;
}

__global__ void count_all_kernel(const int* __restrict__ dst_aa,
                                 const int* __restrict__ src_at,
                                 const int* __restrict__ dst_at,
                                 const int* __restrict__ src_ta,
                                 const int* __restrict__ dst_ta) {
    constexpr int G_AA = E_AA / 4, G_AT = E_AT / 4, G_TA = E_TA / 4;
    int i = blockIdx.x * blockDim.x + threadIdx.x;
    const int* p; int off, j;
    if (i < G_AA)                           { p = dst_aa; off = OFF_AA;   j = i; }
    else if (i < G_AA + G_AT)               { p = src_at; off = OFF_AT_S; j = i - G_AA; }
    else if (i < G_AA + 2 * G_AT)           { p = dst_at; off = OFF_AT_D; j = i - G_AA - G_AT; }
    else if (i < G_AA + 2 * G_AT + G_TA)    { p = src_ta; off = OFF_TA_S; j = i - G_AA - 2 * G_AT; }
    else if (i < G_AA + 2 * G_AT + 2*G_TA)  { p = dst_ta; off = OFF_TA_D; j = i - G_AA - 2 * G_AT - G_TA; }
    else return;
    int4 v = *(const int4*)(p + j * 4);
    atomicAdd(&g_cnt[off + v.x], 1);
    atomicAdd(&g_cnt[off + v.y], 1);
    atomicAdd(&g_cnt[off + v.z], 1);
    atomicAdd(&g_cnt[off + v.w], 1);
}

// Precompute composite projections Va/Vt/Vat and bias constants (1 small block).
__global__ __launch_bounds__(512) void precompute_kernel(
        const float* __restrict__ W2_aa, const float* __restrict__ W2_ta,
        const float* __restrict__ W2_at,
        const float* __restrict__ b2_aa, const float* __restrict__ b2_ta,
        const float* __restrict__ b2_at,
        const float* __restrict__ Wp_a, const float* __restrict__ bp_a,
        const float* __restrict__ Wp_t, const float* __restrict__ bp_t) {
    int tid = threadIdx.x;
    if (tid < 384) {
        int mat = tid >> 7, rem = tid & 127;
        int k = rem >> 1, i = rem & 1;
        const float* W  = (mat == 0) ? W2_aa : (mat == 1) ? W2_ta : W2_at;
        const float* Wp = (mat == 2) ? Wp_t : Wp_a;
        float v = 0.f;
#pragma unroll 16
        for (int h = 0; h < H; h++) v = fmaf(W[k * H + h], Wp[h * 2 + i], v);
        float* V = (mat == 0) ? g_Va : (mat == 1) ? g_Vt : g_Vat;
        V[k * 2 + i] = v;
    } else if (tid < 388) {
        int q = tid - 384;           // 0,1: agent; 2,3: target
        int i = q & 1;
        float v;
        if (q < 2) {
            v = bp_a[i];
            for (int k = 0; k < H; k++)
                v = fmaf(b2_aa[k] + b2_ta[k], Wp_a[k * 2 + i], v);
        } else {
            v = bp_t[i];
            for (int k = 0; k < H; k++)
                v = fmaf(b2_at[k], Wp_t[k * 2 + i], v);
        }
        g_cb[q] = v;
    }
}

__global__ __launch_bounds__(1024) void scan_local_kernel() {
    __shared__ int sm[1024];
    int b = blockIdx.x;
    bool isA = (b < NBLK_A);
    int base = isA ? b * 1024 : (b - NBLK_A) * 1024;
    int n = isA ? NA : NT;
    int tid = threadIdx.x;
    int i = base + tid;
    int v = 0;
    if (i < n) {
        if (isA) { v = g_cnt[OFF_AA + i] + g_cnt[OFF_TA_D + i]; g_cur_a[i] = 0; }
        else     { v = g_cnt[OFF_AT_D + i];                     g_cur_t[i] = 0; }
    }
    sm[tid] = v;
    __syncthreads();
#pragma unroll
    for (int off = 1; off < 1024; off <<= 1) {
        int u = (tid >= off) ? sm[tid - off] : 0;
        __syncthreads();
        sm[tid] += u;
        __syncthreads();
    }
    if (i < n) {
        int excl = sm[tid] - v;
        if (isA) g_rs_a[i] = excl; else g_rs_t[i] = excl;
    }
    if (tid == 1023) g_part[b] = sm[1023];
}

__global__ void scan_mid_kernel() {
    __shared__ int sp[NBLK];
    __shared__ int so[NBLK + 2];
    int tid = threadIdx.x;
    if (tid < NBLK) sp[tid] = g_part[tid];
    __syncthreads();
    if (tid == 0) {
        int s = 0;
        for (int b = 0; b < NBLK_A; b++) { so[b] = s; s += sp[b]; }
        so[NBLK] = s;
        s = 0;
        for (int b = NBLK_A; b < NBLK; b++) { so[b] = s; s += sp[b]; }
        so[NBLK + 1] = s;
    }
    __syncthreads();
    if (tid < NBLK) g_partscan[tid] = so[tid];
    if (tid == 0) { g_rs_a[NA] = so[NBLK]; g_rs_t[NT] = so[NBLK + 1]; }
}

__global__ __launch_bounds__(1024) void scan_add_kernel() {
    int b = blockIdx.x;
    if (b == 0) return;
    bool isA = (b < NBLK_A);
    if (!isA && b == NBLK_A) return;
    int base = isA ? b * 1024 : (b - NBLK_A) * 1024;
    int n = isA ? NA : NT;
    int i = base + threadIdx.x;
    int off = g_partscan[b];
    if (i < n) { if (isA) g_rs_a[i] += off; else g_rs_t[i] += off; }
}

__global__ void fill_kernel(const int* __restrict__ src_aa, const int* __restrict__ dst_aa,
                            const int* __restrict__ src_ta, const int* __restrict__ dst_ta,
                            const int* __restrict__ src_at, const int* __restrict__ dst_at) {
    int i = blockIdx.x * blockDim.x + threadIdx.x;
    if (i < E_AA) {
        int s = src_aa[i], d = dst_aa[i];
        float w = rsqrtf((float)g_cnt[OFF_AA + s] + 1.0f)
                * rsqrtf((float)g_cnt[OFF_AA + d] + 1.0f);
        int pos = g_rs_a[d] + atomicAdd(&g_cur_a[d], 1);
        g_ent_a[pos] = make_int2(s, __float_as_int(w));
    } else if (i < E_AA + E_TA) {
        int j = i - E_AA;
        int s = src_ta[j], d = dst_ta[j];
        float w = rsqrtf((float)g_cnt[OFF_TA_S + s])
                * rsqrtf((float)g_cnt[OFF_TA_D + d]);
        int pos = g_rs_a[d] + atomicAdd(&g_cur_a[d], 1);
        g_ent_a[pos] = make_int2(NA + s, __float_as_int(w));
    } else if (i < E_AA + E_TA + E_AT) {
        int j = i - E_AA - E_TA;
        int s = src_at[j], d = dst_at[j];
        float w = rsqrtf((float)g_cnt[OFF_AT_S + s])
                * rsqrtf((float)g_cnt[OFF_AT_D + d]);
        int pos = g_rs_t[d] + atomicAdd(&g_cur_t[d], 1);
        g_ent_t[pos] = make_int2(s, __float_as_int(w));
    }
}

// Layer-1 agent transform (dual weights). 512 threads, BM=64, 128 cols.
__global__ __launch_bounds__(512, 3) void transform_agent_kernel(
        const float4* __restrict__ x,
        const float* __restrict__ Wa, const float* __restrict__ Wb) {
    constexpr int K = DIN;
    __shared__ float xs[64][K];
    __shared__ float Ws[K][128];
    int tid = threadIdx.x;
    int row0 = blockIdx.x * 64;
    for (int i = tid; i < K * 64; i += 512) {
        int k = i >> 6, c = i & 63;
        Ws[k][c]      = Wa[i];
        Ws[k][c + 64] = Wb[i];
    }
    constexpr int KV = K / 4;
    for (int i = tid; i < 64 * KV; i += 512) {
        int r = i / KV, kv = i - r * KV;
        int row = row0 + r;
        float4 v = (row < NA) ? x[(size_t)row * KV + kv] : make_float4(0.f, 0.f, 0.f, 0.f);
        *(float4*)&xs[r][kv * 4] = v;
    }
    __syncthreads();
    int ty = tid >> 5, tx = tid & 31;
    int r0 = ty * 4, c0 = tx * 4;
    float acc[4][4];
#pragma unroll
    for (int i = 0; i < 4; i++)
#pragma unroll
        for (int j = 0; j < 4; j++) acc[i][j] = 0.f;
#pragma unroll 4
    for (int k = 0; k < K; k++) {
        float w[4];
        *(float4*)&w[0] = *(float4*)&Ws[k][c0];
#pragma unroll
        for (int i = 0; i < 4; i++) {
            float xv = xs[r0 + i][k];
#pragma unroll
            for (int j = 0; j < 4; j++) acc[i][j] = fmaf(xv, w[j], acc[i][j]);
        }
    }
    bool is_a = (c0 < 64);
    int cc = is_a ? c0 : (c0 - 64);
#pragma unroll
    for (int i = 0; i < 4; i++) {
        int row = row0 + r0 + i;
        if (row >= NA) continue;
        __half2 h0 = __floats2half2_rn(acc[i][0], acc[i][1]);
        __half2 h1 = __floats2half2_rn(acc[i][2], acc[i][3]);
        uint2 hpk; hpk.x = *(unsigned*)&h0; hpk.y = *(unsigned*)&h1;
        if (is_a) *(uint2*)(g_h16_A  + (size_t)row * H + cc) = hpk;
        else      *(uint2*)(g_h16_at + (size_t)row * H + cc) = hpk;
    }
}

// Layer-1 target transform -> g_h16_A rows [NA, NA+NT). 256 threads.
__global__ __launch_bounds__(256, 4) void transform_target_kernel(
        const float4* __restrict__ x, const float* __restrict__ W) {
    constexpr int K = DIN;
    __shared__ float xs[64][K];
    __shared__ float Ws[K][64];
    int tid = threadIdx.x;
    int row0 = blockIdx.x * 64;
    for (int i = tid; i < K * 64; i += 256) {
        int k = i >> 6, c = i & 63;
        Ws[k][c] = W[i];
    }
    constexpr int KV = K / 4;
    for (int i = tid; i < 64 * KV; i += 256) {
        int r = i / KV, kv = i - r * KV;
        int row = row0 + r;
        float4 v = (row < NT) ? x[(size_t)row * KV + kv] : make_float4(0.f, 0.f, 0.f, 0.f);
        *(float4*)&xs[r][kv * 4] = v;
    }
    __syncthreads();
    int ty = tid >> 4, tx = tid & 15;
    int r0 = ty * 4, c0 = tx * 4;
    float acc[4][4];
#pragma unroll
    for (int i = 0; i < 4; i++)
#pragma unroll
        for (int j = 0; j < 4; j++) acc[i][j] = 0.f;
#pragma unroll 4
    for (int k = 0; k < K; k++) {
        float w[4];
        *(float4*)&w[0] = *(float4*)&Ws[k][c0];
#pragma unroll
        for (int i = 0; i < 4; i++) {
            float xv = xs[r0 + i][k];
#pragma unroll
            for (int j = 0; j < 4; j++) acc[i][j] = fmaf(xv, w[j], acc[i][j]);
        }
    }
#pragma unroll
    for (int i = 0; i < 4; i++) {
        int row = row0 + r0 + i;
        if (row >= NT) continue;
        __half2 h0 = __floats2half2_rn(acc[i][0], acc[i][1]);
        __half2 h1 = __floats2half2_rn(acc[i][2], acc[i][3]);
        uint2 u; u.x = *(unsigned*)&h0; u.y = *(unsigned*)&h1;
        *(uint2*)(g_h16_A + (size_t)(NA + row) * H + c0) = u;
    }
}

// Warp gather: accumulate weighted fp16 rows (single accumulator).
__device__ __forceinline__ void gather_seg(const int2* __restrict__ ent,
                                           const __half* __restrict__ feat,
                                           int beg, int end, int grp, int sub,
                                           float* a) {
    for (int p = beg + grp; p < end; p += 8) {
        int p2 = p + 4;
        int2 e1 = __ldg(&ent[p]);
        int2 e2 = (p2 < end) ? __ldg(&ent[p2]) : make_int2(0, 0);
        float w1 = __int_as_float(e1.y);
        float w2 = __int_as_float(e2.y);
        uint4 r1 = *(const uint4*)(feat + (size_t)e1.x * H + sub * 8);
        uint4 r2 = *(const uint4*)(feat + (size_t)e2.x * H + sub * 8);
        float2 f;
        f = __half22float2(*(__half2*)&r1.x); a[0] = fmaf(f.x, w1, a[0]); a[1] = fmaf(f.y, w1, a[1]);
        f = __half22float2(*(__half2*)&r1.y); a[2] = fmaf(f.x, w1, a[2]); a[3] = fmaf(f.y, w1, a[3]);
        f = __half22float2(*(__half2*)&r1.z); a[4] = fmaf(f.x, w1, a[4]); a[5] = fmaf(f.y, w1, a[5]);
        f = __half22float2(*(__half2*)&r1.w); a[6] = fmaf(f.x, w1, a[6]); a[7] = fmaf(f.y, w1, a[7]);
        f = __half22float2(*(__half2*)&r2.x); a[0] = fmaf(f.x, w2, a[0]); a[1] = fmaf(f.y, w2, a[1]);
        f = __half22float2(*(__half2*)&r2.y); a[2] = fmaf(f.x, w2, a[2]); a[3] = fmaf(f.y, w2, a[3]);
        f = __half22float2(*(__half2*)&r2.z); a[4] = fmaf(f.x, w2, a[4]); a[5] = fmaf(f.y, w2, a[5]);
        f = __half22float2(*(__half2*)&r2.w); a[6] = fmaf(f.x, w2, a[6]); a[7] = fmaf(f.y, w2, a[7]);
    }
#pragma unroll
    for (int j = 0; j < 8; j++) {
        a[j] += __shfl_down_sync(0xFFFFFFFFu, a[j], 16);
        a[j] += __shfl_down_sync(0xFFFFFFFFu, a[j], 8);
    }
}

// Warp gather with dual accumulators split by src idx < NA (aa vs ta relation).
__device__ __forceinline__ void gather_seg2(const int2* __restrict__ ent,
                                            const __half* __restrict__ feat,
                                            int beg, int end, int grp, int sub,
                                            float* a1, float* a2) {
    for (int p = beg + grp; p < end; p += 8) {
        int p2 = p + 4;
        int2 e1 = __ldg(&ent[p]);
        int2 e2 = (p2 < end) ? __ldg(&ent[p2]) : make_int2(0, 0);
        float w1 = __int_as_float(e1.y);
        float w2 = __int_as_float(e2.y);
        float m1a = (e1.x < NA) ? w1 : 0.f; float m1b = w1 - m1a;
        float m2a = (e2.x < NA) ? w2 : 0.f; float m2b = w2 - m2a;
        uint4 r1 = *(const uint4*)(feat + (size_t)e1.x * H + sub * 8);
        uint4 r2 = *(const uint4*)(feat + (size_t)e2.x * H + sub * 8);
        float2 f;
        f = __half22float2(*(__half2*)&r1.x);
        a1[0] = fmaf(f.x, m1a, a1[0]); a2[0] = fmaf(f.x, m1b, a2[0]);
        a1[1] = fmaf(f.y, m1a, a1[1]); a2[1] = fmaf(f.y, m1b, a2[1]);
        f = __half22float2(*(__half2*)&r1.y);
        a1[2] = fmaf(f.x, m1a, a1[2]); a2[2] = fmaf(f.x, m1b, a2[2]);
        a1[3] = fmaf(f.y, m1a, a1[3]); a2[3] = fmaf(f.y, m1b, a2[3]);
        f = __half22float2(*(__half2*)&r1.z);
        a1[4] = fmaf(f.x, m1a, a1[4]); a2[4] = fmaf(f.x, m1b, a2[4]);
        a1[5] = fmaf(f.y, m1a, a1[5]); a2[5] = fmaf(f.y, m1b, a2[5]);
        f = __half22float2(*(__half2*)&r1.w);
        a1[6] = fmaf(f.x, m1a, a1[6]); a2[6] = fmaf(f.x, m1b, a2[6]);
        a1[7] = fmaf(f.y, m1a, a1[7]); a2[7] = fmaf(f.y, m1b, a2[7]);
        f = __half22float2(*(__half2*)&r2.x);
        a1[0] = fmaf(f.x, m2a, a1[0]); a2[0] = fmaf(f.x, m2b, a2[0]);
        a1[1] = fmaf(f.y, m2a, a1[1]); a2[1] = fmaf(f.y, m2b, a2[1]);
        f = __half22float2(*(__half2*)&r2.y);
        a1[2] = fmaf(f.x, m2a, a1[2]); a2[2] = fmaf(f.x, m2b, a2[2]);
        a1[3] = fmaf(f.y, m2a, a1[3]); a2[3] = fmaf(f.y, m2b, a2[3]);
        f = __half22float2(*(__half2*)&r2.z);
        a1[4] = fmaf(f.x, m2a, a1[4]); a2[4] = fmaf(f.x, m2b, a2[4]);
        a1[5] = fmaf(f.y, m2a, a1[5]); a2[5] = fmaf(f.y, m2b, a2[5]);
        f = __half22float2(*(__half2*)&r2.w);
        a1[6] = fmaf(f.x, m2a, a1[6]); a2[6] = fmaf(f.x, m2b, a2[6]);
        a1[7] = fmaf(f.y, m2a, a1[7]); a2[7] = fmaf(f.y, m2b, a2[7]);
    }
#pragma unroll
    for (int j = 0; j < 8; j++) {
        a1[j] += __shfl_down_sync(0xFFFFFFFFu, a1[j], 16);
        a1[j] += __shfl_down_sync(0xFFFFFFFFu, a1[j], 8);
        a2[j] += __shfl_down_sync(0xFFFFFFFFu, a2[j], 16);
        a2[j] += __shfl_down_sync(0xFFFFFFFFu, a2[j], 8);
    }
}

// Layer-1 aggregation -> relu -> fp16 g_frelu (unified rows).
__global__ __launch_bounds__(256) void agg1_kernel(const float* __restrict__ b_aa,
                                                   const float* __restrict__ b_ta,
                                                   const float* __restrict__ b_at) {
    int gw = (blockIdx.x * 256 + threadIdx.x) >> 5;
    int lane = threadIdx.x & 31;
    int grp = lane >> 3, sub = lane & 7;
    float a[8];
#pragma unroll
    for (int j = 0; j < 8; j++) a[j] = 0.f;
    if (gw < NA) {
        gather_seg(g_ent_a, g_h16_A, g_rs_a[gw], g_rs_a[gw + 1], grp, sub, a);
        if (grp == 0) {
            float dd = 1.0f / ((float)g_cnt[OFF_AA + gw] + 1.0f);
            uint4 rs = *(const uint4*)(g_h16_A + (size_t)gw * H + sub * 8);
            float2 s0 = __half22float2(*(__half2*)&rs.x);
            float2 s1 = __half22float2(*(__half2*)&rs.y);
            float2 s2 = __half22float2(*(__half2*)&rs.z);
            float2 s3 = __half22float2(*(__half2*)&rs.w);
            float sv[8] = {s0.x, s0.y, s1.x, s1.y, s2.x, s2.y, s3.x, s3.y};
            int c = sub * 8;
            float r[8];
#pragma unroll
            for (int j = 0; j < 8; j++)
                r[j] = fmaxf(a[j] + dd * sv[j] + b_aa[c + j] + b_ta[c + j], 0.f);
            __half2 h0 = __floats2half2_rn(r[0], r[1]);
            __half2 h1 = __floats2half2_rn(r[2], r[3]);
            __half2 h2 = __floats2half2_rn(r[4], r[5]);
            __half2 h3 = __floats2half2_rn(r[6], r[7]);
            uint4 u; u.x = *(unsigned*)&h0; u.y = *(unsigned*)&h1;
            u.z = *(unsigned*)&h2; u.w = *(unsigned*)&h3;
            *(uint4*)(g_frelu + (size_t)gw * H + c) = u;
        }
    } else if (gw < NA + NT) {
        int node = gw - NA;
        gather_seg(g_ent_t, g_h16_at, g_rs_t[node], g_rs_t[node + 1], grp, sub, a);
        if (grp == 0) {
            int c = sub * 8;
            float r[8];
#pragma unroll
            for (int j = 0; j < 8; j++) r[j] = fmaxf(a[j] + b_at[c + j], 0.f);
            __half2 h0 = __floats2half2_rn(r[0], r[1]);
            __half2 h1 = __floats2half2_rn(r[2], r[3]);
            __half2 h2 = __floats2half2_rn(r[4], r[5]);
            __half2 h3 = __floats2half2_rn(r[6], r[7]);
            uint4 u; u.x = *(unsigned*)&h0; u.y = *(unsigned*)&h1;
            u.z = *(unsigned*)&h2; u.w = *(unsigned*)&h3;
            *(uint4*)(g_frelu + (size_t)(NA + node) * H + c) = u;
        }
    }
}

// Layer-2: gather g_frelu, project via composite Va/Vt/Vat -> out directly.
__global__ __launch_bounds__(256) void agg2_kernel(float* __restrict__ out) {
    int gw = (blockIdx.x * 256 + threadIdx.x) >> 5;
    int lane = threadIdx.x & 31;
    int grp = lane >> 3, sub = lane & 7;
    float p0 = 0.f, p1 = 0.f;
    float bias0, bias1;
    if (gw < NA) {
        float a1[8], a2[8];
#pragma unroll
        for (int j = 0; j < 8; j++) { a1[j] = 0.f; a2[j] = 0.f; }
        gather_seg2(g_ent_a, g_frelu, g_rs_a[gw], g_rs_a[gw + 1], grp, sub, a1, a2);
        if (grp == 0) {
            float dd = 1.0f / ((float)g_cnt[OFF_AA + gw] + 1.0f);
            uint4 rs = *(const uint4*)(g_frelu + (size_t)gw * H + sub * 8);
            float2 s0 = __half22float2(*(__half2*)&rs.x);
            float2 s1 = __half22float2(*(__half2*)&rs.y);
            float2 s2 = __half22float2(*(__half2*)&rs.z);
            float2 s3 = __half22float2(*(__half2*)&rs.w);
            float sv[8] = {s0.x, s0.y, s1.x, s1.y, s2.x, s2.y, s3.x, s3.y};
            int c = sub * 8;
#pragma unroll
            for (int j = 0; j < 8; j++) {
                float v1 = a1[j] + dd * sv[j];
                p0 = fmaf(v1, g_Va[(c + j) * 2 + 0], p0);
                p1 = fmaf(v1, g_Va[(c + j) * 2 + 1], p1);
                p0 = fmaf(a2[j], g_Vt[(c + j) * 2 + 0], p0);
                p1 = fmaf(a2[j], g_Vt[(c + j) * 2 + 1], p1);
            }
        }
        bias0 = g_cb[0]; bias1 = g_cb[1];
    } else if (gw < NA + NT) {
        int node = gw - NA;
        float a[8];
#pragma unroll
        for (int j = 0; j < 8; j++) a[j] = 0.f;
        gather_seg(g_ent_t, g_frelu, g_rs_t[node], g_rs_t[node + 1], grp, sub, a);
        if (grp == 0) {
            int c = sub * 8;
#pragma unroll
            for (int j = 0; j < 8; j++) {
                p0 = fmaf(a[j], g_Vat[(c + j) * 2 + 0], p0);
                p1 = fmaf(a[j], g_Vat[(c + j) * 2 + 1], p1);
            }
        }
        bias0 = g_cb[2]; bias1 = g_cb[3];
    } else return;
#pragma unroll
    for (int off = 4; off; off >>= 1) {
        p0 += __shfl_down_sync(0xFFFFFFFFu, p0, off);
        p1 += __shfl_down_sync(0xFFFFFFFFu, p1, off);
    }
    if (lane == 0)
        *(float2*)(out + (size_t)gw * 2) = make_float2(p0 + bias0, p1 + bias1);
}

// ---------------------------------------------------------------------------
static inline int cdiv(long long a, int b) { return (int)((a + b - 1) / b); }

extern "C" void kernel_launch(void* const* d_in, const int* in_sizes, int n_in,
                              void* d_out, int out_size) {
    const float* x_agent  = (const float*)d_in[1];
    const float* x_target = (const float*)d_in[2];
    const int* src_aa = (const int*)d_in[3];
    const int* dst_aa = (const int*)d_in[4];
    const int* src_at = (const int*)d_in[5];
    const int* dst_at = (const int*)d_in[6];
    const int* src_ta = (const int*)d_in[7];
    const int* dst_ta = (const int*)d_in[8];
    const float* W1_aa = (const float*)d_in[9];
    const float* b1_aa = (const float*)d_in[10];
    const float* W1_at = (const float*)d_in[11];
    const float* b1_at = (const float*)d_in[12];
    const float* W1_ta = (const float*)d_in[13];
    const float* b1_ta = (const float*)d_in[14];
    const float* W2_aa = (const float*)d_in[15];
    const float* b2_aa = (const float*)d_in[16];
    const float* W2_at = (const float*)d_in[17];
    const float* b2_at = (const float*)d_in[18];
    const float* W2_ta = (const float*)d_in[19];
    const float* b2_ta = (const float*)d_in[20];
    const float* Wp_agent  = (const float*)d_in[21];
    const float* bp_agent  = (const float*)d_in[22];
    const float* Wp_target = (const float*)d_in[23];
    const float* bp_target = (const float*)d_in[24];
    float* out = (float*)d_out;

    static cudaStream_t s2 = nullptr;
    static cudaEvent_t evFork = nullptr, evL1 = nullptr;
    if (s2 == nullptr) {
        cudaStreamCreateWithFlags(&s2, cudaStreamNonBlocking);
        cudaEventCreateWithFlags(&evFork, cudaEventDisableTiming);
        cudaEventCreateWithFlags(&evL1,   cudaEventDisableTiming);
    }

    // ---- fork: precompute + layer-1 transforms on s2 (inputs/weights only) ----
    cudaEventRecord(evFork, 0);
    cudaStreamWaitEvent(s2, evFork, 0);
    precompute_kernel<<<1, 512, 0, s2>>>(W2_aa, W2_ta, W2_at, b2_aa, b2_ta, b2_at,
                                         Wp_agent, bp_agent, Wp_target, bp_target);
    transform_agent_kernel<<<cdiv(NA, 64), 512, 0, s2>>>(
        (const float4*)x_agent, W1_aa, W1_at);
    transform_target_kernel<<<cdiv(NT, 64), 256, 0, s2>>>(
        (const float4*)x_target, W1_ta);
    cudaEventRecord(evL1, s2);

    // ---- main stream: CSR build ----
    zero_cnt_kernel<<<cdiv(NTOT, 256), 256>>>();
    constexpr long long CNT_G = (E_AA + 2LL * E_AT + 2LL * E_TA) / 4;
    count_all_kernel<<<cdiv(CNT_G, 256), 256>>>(dst_aa, src_at, dst_at, src_ta, dst_ta);
    scan_local_kernel<<<NBLK, 1024>>>();
    scan_mid_kernel<<<1, 128>>>();
    scan_add_kernel<<<NBLK, 1024>>>();
    constexpr long long E_TOT = E_AA + E_TA + E_AT;
    fill_kernel<<<cdiv(E_TOT, 256), 256>>>(src_aa, dst_aa, src_ta, dst_ta, src_at, dst_at);

    // ---- join, then the two aggregation passes (layer 2 fully collapsed) ----
    cudaStreamWaitEvent(0, evL1, 0);
    constexpr long long AGG_THREADS = (long long)(NA + NT) * 32;
    agg1_kernel<<<cdiv(AGG_THREADS, 256), 256>>>(b1_aa, b1_ta, b1_at);
    agg2_kernel<<<cdiv(AGG_THREADS, 256), 256>>>(out);
}

// round 17
// speedup vs baseline: 1.2185x; 1.0408x over previous
#include <cuda_runtime.h>
#include <cuda_fp16.h>
#include <math.h>

constexpr int NA = 50000;
constexpr int NT = 25000;
constexpr int DIN = 32;
constexpr int H = 64;
constexpr int E_AA = 800000;
constexpr int E_AT = 400000;
constexpr int E_TA = 400000;

constexpr int OFF_AA   = 0;
constexpr int OFF_AT_S = NA;
constexpr int OFF_TA_D = 2 * NA;
constexpr int OFF_AT_D = 3 * NA;
constexpr int OFF_TA_S = 3 * NA + NT;
constexpr int NTOT = 3 * NA + 2 * NT;

constexpr int NBLK_A = (NA + 1023) / 1024;
constexpr int NBLK_T = (NT + 1023) / 1024;
constexpr int NBLK   = NBLK_A + NBLK_T;

// scratch
__device__ int    g_cnt[NTOT];
__device__ __half g_h16_A[(size_t)(NA + NT) * H];   // layer1 feats: [0,NA)=x@W1_aa, [NA,..)=x_t@W1_ta
__device__ __half g_h16_at[(size_t)NA * H];         // x@W1_at (agent->target)
__device__ float4 g_q[NA + NT];                     // per-node projections:
                                                    //  agents: {qa0,qa1,qat0,qat1}, targets: {qt0,qt1,0,0}
// composite projection matrices and bias constants
__device__ float g_Va[H * 2];    // W2_aa @ Wp_agent
__device__ float g_Vt[H * 2];    // W2_ta @ Wp_agent
__device__ float g_Vat[H * 2];   // W2_at @ Wp_target
__device__ float g_cb[4];        // {agent bias0, agent bias1, target bias0, target bias1}
// CSR (built once per launch)
__device__ int  g_rs_a[NA + 1];
__device__ int  g_rs_t[NT + 1];
__device__ int  g_cur_a[NA];
__device__ int  g_cur_t[NT];
__device__ int2 g_ent_a[E_AA + E_TA];
__device__ int2 g_ent_t[E_AT];
__device__ int  g_part[NBLK];
__device__ int  g_partscan[NBLK];

// ---------------------------------------------------------------------------
__global__ void zero_cnt_kernel() {
    int i = blockIdx.x * blockDim.x + threadIdx.x;
    if (i < NTOT) g_cnt[i] = 0;
}

__global__ void count_all_kernel(const int* __restrict__ dst_aa,
                                 const int* __restrict__ src_at,
                                 const int* __restrict__ dst_at,
                                 const int* __restrict__ src_ta,
                                 const int* __restrict__ dst_ta) {
    constexpr int G_AA = E_AA / 4, G_AT = E_AT / 4, G_TA = E_TA / 4;
    int i = blockIdx.x * blockDim.x + threadIdx.x;
    const int* p; int off, j;
    if (i < G_AA)                           { p = dst_aa; off = OFF_AA;   j = i; }
    else if (i < G_AA + G_AT)               { p = src_at; off = OFF_AT_S; j = i - G_AA; }
    else if (i < G_AA + 2 * G_AT)           { p = dst_at; off = OFF_AT_D; j = i - G_AA - G_AT; }
    else if (i < G_AA + 2 * G_AT + G_TA)    { p = src_ta; off = OFF_TA_S; j = i - G_AA - 2 * G_AT; }
    else if (i < G_AA + 2 * G_AT + 2*G_TA)  { p = dst_ta; off = OFF_TA_D; j = i - G_AA - 2 * G_AT - G_TA; }
    else return;
    int4 v = *(const int4*)(p + j * 4);
    atomicAdd(&g_cnt[off + v.x], 1);
    atomicAdd(&g_cnt[off + v.y], 1);
    atomicAdd(&g_cnt[off + v.z], 1);
    atomicAdd(&g_cnt[off + v.w], 1);
}

// Precompute composite projections Va/Vt/Vat and bias constants (1 small block).
__global__ __launch_bounds__(512) void precompute_kernel(
        const float* __restrict__ W2_aa, const float* __restrict__ W2_ta,
        const float* __restrict__ W2_at,
        const float* __restrict__ b2_aa, const float* __restrict__ b2_ta,
        const float* __restrict__ b2_at,
        const float* __restrict__ Wp_a, const float* __restrict__ bp_a,
        const float* __restrict__ Wp_t, const float* __restrict__ bp_t) {
    int tid = threadIdx.x;
    if (tid < 384) {
        int mat = tid >> 7, rem = tid & 127;
        int k = rem >> 1, i = rem & 1;
        const float* W  = (mat == 0) ? W2_aa : (mat == 1) ? W2_ta : W2_at;
        const float* Wp = (mat == 2) ? Wp_t : Wp_a;
        float v = 0.f;
#pragma unroll 16
        for (int h = 0; h < H; h++) v = fmaf(W[k * H + h], Wp[h * 2 + i], v);
        float* V = (mat == 0) ? g_Va : (mat == 1) ? g_Vt : g_Vat;
        V[k * 2 + i] = v;
    } else if (tid < 388) {
        int q = tid - 384;
        int i = q & 1;
        float v;
        if (q < 2) {
            v = bp_a[i];
            for (int k = 0; k < H; k++)
                v = fmaf(b2_aa[k] + b2_ta[k], Wp_a[k * 2 + i], v);
        } else {
            v = bp_t[i];
            for (int k = 0; k < H; k++)
                v = fmaf(b2_at[k], Wp_t[k * 2 + i], v);
        }
        g_cb[q] = v;
    }
}

__global__ __launch_bounds__(1024) void scan_local_kernel() {
    __shared__ int sm[1024];
    int b = blockIdx.x;
    bool isA = (b < NBLK_A);
    int base = isA ? b * 1024 : (b - NBLK_A) * 1024;
    int n = isA ? NA : NT;
    int tid = threadIdx.x;
    int i = base + tid;
    int v = 0;
    if (i < n) {
        if (isA) { v = g_cnt[OFF_AA + i] + g_cnt[OFF_TA_D + i]; g_cur_a[i] = 0; }
        else     { v = g_cnt[OFF_AT_D + i];                     g_cur_t[i] = 0; }
    }
    sm[tid] = v;
    __syncthreads();
#pragma unroll
    for (int off = 1; off < 1024; off <<= 1) {
        int u = (tid >= off) ? sm[tid - off] : 0;
        __syncthreads();
        sm[tid] += u;
        __syncthreads();
    }
    if (i < n) {
        int excl = sm[tid] - v;
        if (isA) g_rs_a[i] = excl; else g_rs_t[i] = excl;
    }
    if (tid == 1023) g_part[b] = sm[1023];
}

__global__ void scan_mid_kernel() {
    __shared__ int sp[NBLK];
    __shared__ int so[NBLK + 2];
    int tid = threadIdx.x;
    if (tid < NBLK) sp[tid] = g_part[tid];
    __syncthreads();
    if (tid == 0) {
        int s = 0;
        for (int b = 0; b < NBLK_A; b++) { so[b] = s; s += sp[b]; }
        so[NBLK] = s;
        s = 0;
        for (int b = NBLK_A; b < NBLK; b++) { so[b] = s; s += sp[b]; }
        so[NBLK + 1] = s;
    }
    __syncthreads();
    if (tid < NBLK) g_partscan[tid] = so[tid];
    if (tid == 0) { g_rs_a[NA] = so[NBLK]; g_rs_t[NT] = so[NBLK + 1]; }
}

__global__ __launch_bounds__(1024) void scan_add_kernel() {
    int b = blockIdx.x;
    if (b == 0) return;
    bool isA = (b < NBLK_A);
    if (!isA && b == NBLK_A) return;
    int base = isA ? b * 1024 : (b - NBLK_A) * 1024;
    int n = isA ? NA : NT;
    int i = base + threadIdx.x;
    int off = g_partscan[b];
    if (i < n) { if (isA) g_rs_a[i] += off; else g_rs_t[i] += off; }
}

__global__ void fill_kernel(const int* __restrict__ src_aa, const int* __restrict__ dst_aa,
                            const int* __restrict__ src_ta, const int* __restrict__ dst_ta,
                            const int* __restrict__ src_at, const int* __restrict__ dst_at) {
    int i = blockIdx.x * blockDim.x + threadIdx.x;
    if (i < E_AA) {
        int s = src_aa[i], d = dst_aa[i];
        float w = rsqrtf((float)g_cnt[OFF_AA + s] + 1.0f)
                * rsqrtf((float)g_cnt[OFF_AA + d] + 1.0f);
        int pos = g_rs_a[d] + atomicAdd(&g_cur_a[d], 1);
        g_ent_a[pos] = make_int2(s, __float_as_int(w));
    } else if (i < E_AA + E_TA) {
        int j = i - E_AA;
        int s = src_ta[j], d = dst_ta[j];
        float w = rsqrtf((float)g_cnt[OFF_TA_S + s])
                * rsqrtf((float)g_cnt[OFF_TA_D + d]);
        int pos = g_rs_a[d] + atomicAdd(&g_cur_a[d], 1);
        g_ent_a[pos] = make_int2(NA + s, __float_as_int(w));
    } else if (i < E_AA + E_TA + E_AT) {
        int j = i - E_AA - E_TA;
        int s = src_at[j], d = dst_at[j];
        float w = rsqrtf((float)g_cnt[OFF_AT_S + s])
                * rsqrtf((float)g_cnt[OFF_AT_D + d]);
        int pos = g_rs_t[d] + atomicAdd(&g_cur_t[d], 1);
        g_ent_t[pos] = make_int2(s, __float_as_int(w));
    }
}

// Layer-1 agent transform (dual weights). 512 threads, BM=64, 128 cols.
__global__ __launch_bounds__(512, 3) void transform_agent_kernel(
        const float4* __restrict__ x,
        const float* __restrict__ Wa, const float* __restrict__ Wb) {
    constexpr int K = DIN;
    __shared__ float xs[64][K];
    __shared__ float Ws[K][128];
    int tid = threadIdx.x;
    int row0 = blockIdx.x * 64;
    for (int i = tid; i < K * 64; i += 512) {
        int k = i >> 6, c = i & 63;
        Ws[k][c]      = Wa[i];
        Ws[k][c + 64] = Wb[i];
    }
    constexpr int KV = K / 4;
    for (int i = tid; i < 64 * KV; i += 512) {
        int r = i / KV, kv = i - r * KV;
        int row = row0 + r;
        float4 v = (row < NA) ? x[(size_t)row * KV + kv] : make_float4(0.f, 0.f, 0.f, 0.f);
        *(float4*)&xs[r][kv * 4] = v;
    }
    __syncthreads();
    int ty = tid >> 5, tx = tid & 31;
    int r0 = ty * 4, c0 = tx * 4;
    float acc[4][4];
#pragma unroll
    for (int i = 0; i < 4; i++)
#pragma unroll
        for (int j = 0; j < 4; j++) acc[i][j] = 0.f;
#pragma unroll 4
    for (int k = 0; k < K; k++) {
        float w[4];
        *(float4*)&w[0] = *(float4*)&Ws[k][c0];
#pragma unroll
        for (int i = 0; i < 4; i++) {
            float xv = xs[r0 + i][k];
#pragma unroll
            for (int j = 0; j < 4; j++) acc[i][j] = fmaf(xv, w[j], acc[i][j]);
        }
    }
    bool is_a = (c0 < 64);
    int cc = is_a ? c0 : (c0 - 64);
#pragma unroll
    for (int i = 0; i < 4; i++) {
        int row = row0 + r0 + i;
        if (row >= NA) continue;
        __half2 h0 = __floats2half2_rn(acc[i][0], acc[i][1]);
        __half2 h1 = __floats2half2_rn(acc[i][2], acc[i][3]);
        uint2 hpk; hpk.x = *(unsigned*)&h0; hpk.y = *(unsigned*)&h1;
        if (is_a) *(uint2*)(g_h16_A  + (size_t)row * H + cc) = hpk;
        else      *(uint2*)(g_h16_at + (size_t)row * H + cc) = hpk;
    }
}

// Layer-1 target transform -> g_h16_A rows [NA, NA+NT). 256 threads.
__global__ __launch_bounds__(256, 4) void transform_target_kernel(
        const float4* __restrict__ x, const float* __restrict__ W) {
    constexpr int K = DIN;
    __shared__ float xs[64][K];
    __shared__ float Ws[K][64];
    int tid = threadIdx.x;
    int row0 = blockIdx.x * 64;
    for (int i = tid; i < K * 64; i += 256) {
        int k = i >> 6, c = i & 63;
        Ws[k][c] = W[i];
    }
    constexpr int KV = K / 4;
    for (int i = tid; i < 64 * KV; i += 256) {
        int r = i / KV, kv = i - r * KV;
        int row = row0 + r;
        float4 v = (row < NT) ? x[(size_t)row * KV + kv] : make_float4(0.f, 0.f, 0.f, 0.f);
        *(float4*)&xs[r][kv * 4] = v;
    }
    __syncthreads();
    int ty = tid >> 4, tx = tid & 15;
    int r0 = ty * 4, c0 = tx * 4;
    float acc[4][4];
#pragma unroll
    for (int i = 0; i < 4; i++)
#pragma unroll
        for (int j = 0; j < 4; j++) acc[i][j] = 0.f;
#pragma unroll 4
    for (int k = 0; k < K; k++) {
        float w[4];
        *(float4*)&w[0] = *(float4*)&Ws[k][c0];
#pragma unroll
        for (int i = 0; i < 4; i++) {
            float xv = xs[r0 + i][k];
#pragma unroll
            for (int j = 0; j < 4; j++) acc[i][j] = fmaf(xv, w[j], acc[i][j]);
        }
    }
#pragma unroll
    for (int i = 0; i < 4; i++) {
        int row = row0 + r0 + i;
        if (row >= NT) continue;
        __half2 h0 = __floats2half2_rn(acc[i][0], acc[i][1]);
        __half2 h1 = __floats2half2_rn(acc[i][2], acc[i][3]);
        uint2 u; u.x = *(unsigned*)&h0; u.y = *(unsigned*)&h1;
        *(uint2*)(g_h16_A + (size_t)(NA + row) * H + c0) = u;
    }
}

// Warp gather: accumulate weighted fp16 rows (single accumulator).
__device__ __forceinline__ void gather_seg(const int2* __restrict__ ent,
                                           const __half* __restrict__ feat,
                                           int beg, int end, int grp, int sub,
                                           float* a) {
    for (int p = beg + grp; p < end; p += 8) {
        int p2 = p + 4;
        int2 e1 = __ldg(&ent[p]);
        int2 e2 = (p2 < end) ? __ldg(&ent[p2]) : make_int2(0, 0);
        float w1 = __int_as_float(e1.y);
        float w2 = __int_as_float(e2.y);
        uint4 r1 = *(const uint4*)(feat + (size_t)e1.x * H + sub * 8);
        uint4 r2 = *(const uint4*)(feat + (size_t)e2.x * H + sub * 8);
        float2 f;
        f = __half22float2(*(__half2*)&r1.x); a[0] = fmaf(f.x, w1, a[0]); a[1] = fmaf(f.y, w1, a[1]);
        f = __half22float2(*(__half2*)&r1.y); a[2] = fmaf(f.x, w1, a[2]); a[3] = fmaf(f.y, w1, a[3]);
        f = __half22float2(*(__half2*)&r1.z); a[4] = fmaf(f.x, w1, a[4]); a[5] = fmaf(f.y, w1, a[5]);
        f = __half22float2(*(__half2*)&r1.w); a[6] = fmaf(f.x, w1, a[6]); a[7] = fmaf(f.y, w1, a[7]);
        f = __half22float2(*(__half2*)&r2.x); a[0] = fmaf(f.x, w2, a[0]); a[1] = fmaf(f.y, w2, a[1]);
        f = __half22float2(*(__half2*)&r2.y); a[2] = fmaf(f.x, w2, a[2]); a[3] = fmaf(f.y, w2, a[3]);
        f = __half22float2(*(__half2*)&r2.z); a[4] = fmaf(f.x, w2, a[4]); a[5] = fmaf(f.y, w2, a[5]);
        f = __half22float2(*(__half2*)&r2.w); a[6] = fmaf(f.x, w2, a[6]); a[7] = fmaf(f.y, w2, a[7]);
    }
#pragma unroll
    for (int j = 0; j < 8; j++) {
        a[j] += __shfl_down_sync(0xFFFFFFFFu, a[j], 16);
        a[j] += __shfl_down_sync(0xFFFFFFFFu, a[j], 8);
    }
}

// Layer-1 aggregation -> relu -> per-node projections q (float4).
// Agents: q = {r.Va, r.Vat}; Targets: q = {r.Vt, 0}.
__global__ __launch_bounds__(256) void agg1_kernel(const float* __restrict__ b_aa,
                                                   const float* __restrict__ b_ta,
                                                   const float* __restrict__ b_at) {
    int gw = (blockIdx.x * 256 + threadIdx.x) >> 5;
    int lane = threadIdx.x & 31;
    int grp = lane >> 3, sub = lane & 7;
    float a[8];
#pragma unroll
    for (int j = 0; j < 8; j++) a[j] = 0.f;
    float q0 = 0.f, q1 = 0.f, q2 = 0.f, q3 = 0.f;
    if (gw < NA) {
        gather_seg(g_ent_a, g_h16_A, g_rs_a[gw], g_rs_a[gw + 1], grp, sub, a);
        if (grp == 0) {
            float dd = 1.0f / ((float)g_cnt[OFF_AA + gw] + 1.0f);
            uint4 rs = *(const uint4*)(g_h16_A + (size_t)gw * H + sub * 8);
            float2 s0 = __half22float2(*(__half2*)&rs.x);
            float2 s1 = __half22float2(*(__half2*)&rs.y);
            float2 s2 = __half22float2(*(__half2*)&rs.z);
            float2 s3 = __half22float2(*(__half2*)&rs.w);
            float sv[8] = {s0.x, s0.y, s1.x, s1.y, s2.x, s2.y, s3.x, s3.y};
            int c = sub * 8;
#pragma unroll
            for (int j = 0; j < 8; j++) {
                float r = fmaxf(a[j] + dd * sv[j] + b_aa[c + j] + b_ta[c + j], 0.f);
                q0 = fmaf(r, g_Va[(c + j) * 2 + 0], q0);
                q1 = fmaf(r, g_Va[(c + j) * 2 + 1], q1);
                q2 = fmaf(r, g_Vat[(c + j) * 2 + 0], q2);
                q3 = fmaf(r, g_Vat[(c + j) * 2 + 1], q3);
            }
        }
    } else if (gw < NA + NT) {
        int node = gw - NA;
        gather_seg(g_ent_t, g_h16_at, g_rs_t[node], g_rs_t[node + 1], grp, sub, a);
        if (grp == 0) {
            int c = sub * 8;
#pragma unroll
            for (int j = 0; j < 8; j++) {
                float r = fmaxf(a[j] + b_at[c + j], 0.f);
                q0 = fmaf(r, g_Vt[(c + j) * 2 + 0], q0);
                q1 = fmaf(r, g_Vt[(c + j) * 2 + 1], q1);
            }
        }
    } else return;
    // reduce q over the 8 sub-lanes (lanes 0..7 hold partials; others are zero)
#pragma unroll
    for (int off = 4; off; off >>= 1) {
        q0 += __shfl_down_sync(0xFFFFFFFFu, q0, off);
        q1 += __shfl_down_sync(0xFFFFFFFFu, q1, off);
        q2 += __shfl_down_sync(0xFFFFFFFFu, q2, off);
        q3 += __shfl_down_sync(0xFFFFFFFFu, q3, off);
    }
    if (lane == 0) g_q[gw] = make_float4(q0, q1, q2, q3);
}

// Layer-2: gather per-source projections (8 bytes/edge) -> out directly.
__global__ __launch_bounds__(256) void agg2_kernel(float* __restrict__ out) {
    int gw = (blockIdx.x * 256 + threadIdx.x) >> 5;
    int lane = threadIdx.x & 31;
    float p0 = 0.f, p1 = 0.f;
    float bias0, bias1;
    if (gw < NA) {
        int beg = g_rs_a[gw], end = g_rs_a[gw + 1];
        for (int p = beg + lane; p < end; p += 32) {
            int2 e = __ldg(&g_ent_a[p]);
            float w = __int_as_float(e.y);
            float2 qq = *(const float2*)&g_q[e.x];   // qa (agent src) or qt (target src)
            p0 = fmaf(w, qq.x, p0);
            p1 = fmaf(w, qq.y, p1);
        }
        bias0 = g_cb[0]; bias1 = g_cb[1];
    } else if (gw < NA + NT) {
        int node = gw - NA;
        int beg = g_rs_t[node], end = g_rs_t[node + 1];
        for (int p = beg + lane; p < end; p += 32) {
            int2 e = __ldg(&g_ent_t[p]);
            float w = __int_as_float(e.y);
            float2 qq = *(const float2*)((const float*)&g_q[e.x] + 2);   // qat
            p0 = fmaf(w, qq.x, p0);
            p1 = fmaf(w, qq.y, p1);
        }
        bias0 = g_cb[2]; bias1 = g_cb[3];
    } else return;
#pragma unroll
    for (int off = 16; off; off >>= 1) {
        p0 += __shfl_down_sync(0xFFFFFFFFu, p0, off);
        p1 += __shfl_down_sync(0xFFFFFFFFu, p1, off);
    }
    if (lane == 0) {
        if (gw < NA) {
            float dd = 1.0f / ((float)g_cnt[OFF_AA + gw] + 1.0f);   // self-loop term
            float2 qq = *(const float2*)&g_q[gw];
            p0 = fmaf(dd, qq.x, p0);
            p1 = fmaf(dd, qq.y, p1);
        }
        *(float2*)(out + (size_t)gw * 2) = make_float2(p0 + bias0, p1 + bias1);
    }
}

// ---------------------------------------------------------------------------
static inline int cdiv(long long a, int b) { return (int)((a + b - 1) / b); }

extern "C" void kernel_launch(void* const* d_in, const int* in_sizes, int n_in,
                              void* d_out, int out_size) {
    const float* x_agent  = (const float*)d_in[1];
    const float* x_target = (const float*)d_in[2];
    const int* src_aa = (const int*)d_in[3];
    const int* dst_aa = (const int*)d_in[4];
    const int* src_at = (const int*)d_in[5];
    const int* dst_at = (const int*)d_in[6];
    const int* src_ta = (const int*)d_in[7];
    const int* dst_ta = (const int*)d_in[8];
    const float* W1_aa = (const float*)d_in[9];
    const float* b1_aa = (const float*)d_in[10];
    const float* W1_at = (const float*)d_in[11];
    const float* b1_at = (const float*)d_in[12];
    const float* W1_ta = (const float*)d_in[13];
    const float* b1_ta = (const float*)d_in[14];
    const float* W2_aa = (const float*)d_in[15];
    const float* b2_aa = (const float*)d_in[16];
    const float* W2_at = (const float*)d_in[17];
    const float* b2_at = (const float*)d_in[18];
    const float* W2_ta = (const float*)d_in[19];
    const float* b2_ta = (const float*)d_in[20];
    const float* Wp_agent  = (const float*)d_in[21];
    const float* bp_agent  = (const float*)d_in[22];
    const float* Wp_target = (const float*)d_in[23];
    const float* bp_target = (const float*)d_in[24];
    float* out = (float*)d_out;

    static cudaStream_t s2 = nullptr;
    static cudaEvent_t evFork = nullptr, evL1 = nullptr;
    if (s2 == nullptr) {
        cudaStreamCreateWithFlags(&s2, cudaStreamNonBlocking);
        cudaEventCreateWithFlags(&evFork, cudaEventDisableTiming);
        cudaEventCreateWithFlags(&evL1,   cudaEventDisableTiming);
    }

    // ---- fork: precompute + layer-1 transforms on s2 (inputs/weights only) ----
    cudaEventRecord(evFork, 0);
    cudaStreamWaitEvent(s2, evFork, 0);
    precompute_kernel<<<1, 512, 0, s2>>>(W2_aa, W2_ta, W2_at, b2_aa, b2_ta, b2_at,
                                         Wp_agent, bp_agent, Wp_target, bp_target);
    transform_agent_kernel<<<cdiv(NA, 64), 512, 0, s2>>>(
        (const float4*)x_agent, W1_aa, W1_at);
    transform_target_kernel<<<cdiv(NT, 64), 256, 0, s2>>>(
        (const float4*)x_target, W1_ta);
    cudaEventRecord(evL1, s2);

    // ---- main stream: CSR build ----
    zero_cnt_kernel<<<cdiv(NTOT, 256), 256>>>();
    constexpr long long CNT_G = (E_AA + 2LL * E_AT + 2LL * E_TA) / 4;
    count_all_kernel<<<cdiv(CNT_G, 256), 256>>>(dst_aa, src_at, dst_at, src_ta, dst_ta);
    scan_local_kernel<<<NBLK, 1024>>>();
    scan_mid_kernel<<<1, 128>>>();
    scan_add_kernel<<<NBLK, 1024>>>();
    constexpr long long E_TOT = E_AA + E_TA + E_AT;
    fill_kernel<<<cdiv(E_TOT, 256), 256>>>(src_aa, dst_aa, src_ta, dst_ta, src_at, dst_at);

    // ---- join, then the two aggregation passes ----
    cudaStreamWaitEvent(0, evL1, 0);
    constexpr long long AGG_THREADS = (long long)(NA + NT) * 32;
    agg1_kernel<<<cdiv(AGG_THREADS, 256), 256>>>(b1_aa, b1_ta, b1_at);
    agg2_kernel<<<cdiv(AGG_THREADS, 256), 256>>>(out);
}